// round 1
// baseline (speedup 1.0000x reference)
#include <cuda_runtime.h>
#include <math.h>

#define NCLS 256
#define NDIM 256
#define MB   16   // batch rows per block

// Scratch (allocation-free rule: __device__ globals)
__device__ __align__(16) float g_dinvh[NCLS * NDIM];  // 0.5 / D   [k][d]
__device__ __align__(16) float g_cd[NCLS * NDIM];     // c / D     [k][d]
__device__ __align__(16) float g_bias[NCLS];          // -0.5*(sum c^2/D + sum log D)

// ---------------------------------------------------------------------------
// Prep: one block per class k, 256 threads (one per dim)
// ---------------------------------------------------------------------------
__global__ void prep_kernel(const float* __restrict__ centers,
                            const float* __restrict__ Droot) {
    int k = blockIdx.x;
    int d = threadIdx.x;
    int idx = k * NDIM + d;

    float D    = fabsf(Droot[idx]) + 1e-4f;
    float dinv = 1.0f / D;
    float c    = centers[idx];

    g_dinvh[idx] = 0.5f * dinv;
    g_cd[idx]    = c * dinv;

    float p = c * c * dinv + logf(D);

    // block reduce sum over 256 threads
    __shared__ float red[8];
    #pragma unroll
    for (int o = 16; o; o >>= 1) p += __shfl_xor_sync(0xFFFFFFFFu, p, o);
    if ((threadIdx.x & 31) == 0) red[threadIdx.x >> 5] = p;
    __syncthreads();
    if (threadIdx.x < 8) {
        float v = red[threadIdx.x];
        #pragma unroll
        for (int o = 4; o; o >>= 1) v += __shfl_xor_sync(0xFFu, v, o);
        if (threadIdx.x == 0) g_bias[k] = -0.5f * v;
    }
}

// ---------------------------------------------------------------------------
// Main: block = 16 batch rows x 256 classes. 256 threads.
// Thread (mg = t>>6, kk = t&63) owns rows mg*4..+3, classes kk*4..+3.
// logit[b,k] = -sum x^2 * (0.5/D) + sum x * (c/D) + bias[k]
// resp = softmax_k(logit)
// ---------------------------------------------------------------------------
__global__ __launch_bounds__(256, 2)
void gmm_kernel(const float* __restrict__ x, float* __restrict__ out) {
    __shared__ __align__(16) float xs[MB * NDIM];  // 16KB; reused for logits

    const int t  = threadIdx.x;
    const int b0 = blockIdx.x * MB;

    // Cooperative load of x tile (coalesced float4)
    {
        const float4* xg  = (const float4*)(x + (size_t)b0 * NDIM);
        float4*       xsv = (float4*)xs;
        #pragma unroll
        for (int i = 0; i < 4; i++) xsv[i * 256 + t] = xg[i * 256 + t];
    }
    __syncthreads();

    const int kk = t & 63;
    const int mg = t >> 6;

    float acc1[4][4];  // sum x^2 * dinvh
    float acc2[4][4];  // sum x  * cd
    #pragma unroll
    for (int m = 0; m < 4; m++)
        #pragma unroll
        for (int kx = 0; kx < 4; kx++) { acc1[m][kx] = 0.0f; acc2[m][kx] = 0.0f; }

    const float* xsp = xs + mg * 4 * NDIM;
    const float* dhb = g_dinvh + kk * 4 * NDIM;
    const float* cdb = g_cd    + kk * 4 * NDIM;

    #pragma unroll 2
    for (int d = 0; d < NDIM; d += 4) {
        float4 xv[4], x2[4];
        #pragma unroll
        for (int m = 0; m < 4; m++) {
            xv[m] = *(const float4*)(xsp + m * NDIM + d);
            x2[m].x = xv[m].x * xv[m].x;
            x2[m].y = xv[m].y * xv[m].y;
            x2[m].z = xv[m].z * xv[m].z;
            x2[m].w = xv[m].w * xv[m].w;
        }
        #pragma unroll
        for (int kx = 0; kx < 4; kx++) {
            float4 dh = *(const float4*)(dhb + kx * NDIM + d);
            float4 cd = *(const float4*)(cdb + kx * NDIM + d);
            #pragma unroll
            for (int m = 0; m < 4; m++) {
                float a1 = acc1[m][kx];
                a1 = fmaf(x2[m].x, dh.x, a1);
                a1 = fmaf(x2[m].y, dh.y, a1);
                a1 = fmaf(x2[m].z, dh.z, a1);
                a1 = fmaf(x2[m].w, dh.w, a1);
                acc1[m][kx] = a1;
                float a2 = acc2[m][kx];
                a2 = fmaf(xv[m].x, cd.x, a2);
                a2 = fmaf(xv[m].y, cd.y, a2);
                a2 = fmaf(xv[m].z, cd.z, a2);
                a2 = fmaf(xv[m].w, cd.w, a2);
                acc2[m][kx] = a2;
            }
        }
    }

    __syncthreads();  // done reading xs; reuse as logits[16][256]

    {
        float4 bias = *(const float4*)(g_bias + kk * 4);
        #pragma unroll
        for (int m = 0; m < 4; m++) {
            float4 lv;
            lv.x = acc2[m][0] - acc1[m][0] + bias.x;
            lv.y = acc2[m][1] - acc1[m][1] + bias.y;
            lv.z = acc2[m][2] - acc1[m][2] + bias.z;
            lv.w = acc2[m][3] - acc1[m][3] + bias.w;
            *(float4*)(xs + (mg * 4 + m) * NDIM + kk * 4) = lv;
        }
    }
    __syncthreads();

    // Softmax: warp w handles rows w*2, w*2+1; lane owns 8 classes.
    const int w    = t >> 5;
    const int lane = t & 31;
    #pragma unroll
    for (int rr = 0; rr < 2; rr++) {
        int r = w * 2 + rr;
        const float4* lrow = (const float4*)(xs + r * NDIM);
        float4 a = lrow[lane * 2];
        float4 b = lrow[lane * 2 + 1];

        float mx = fmaxf(fmaxf(fmaxf(a.x, a.y), fmaxf(a.z, a.w)),
                         fmaxf(fmaxf(b.x, b.y), fmaxf(b.z, b.w)));
        #pragma unroll
        for (int o = 16; o; o >>= 1) mx = fmaxf(mx, __shfl_xor_sync(0xFFFFFFFFu, mx, o));

        float4 ea, eb;
        ea.x = __expf(a.x - mx); ea.y = __expf(a.y - mx);
        ea.z = __expf(a.z - mx); ea.w = __expf(a.w - mx);
        eb.x = __expf(b.x - mx); eb.y = __expf(b.y - mx);
        eb.z = __expf(b.z - mx); eb.w = __expf(b.w - mx);

        float s = (ea.x + ea.y) + (ea.z + ea.w) + (eb.x + eb.y) + (eb.z + eb.w);
        #pragma unroll
        for (int o = 16; o; o >>= 1) s += __shfl_xor_sync(0xFFFFFFFFu, s, o);

        float inv = 1.0f / s;
        ea.x *= inv; ea.y *= inv; ea.z *= inv; ea.w *= inv;
        eb.x *= inv; eb.y *= inv; eb.z *= inv; eb.w *= inv;

        float4* orow = (float4*)(out + (size_t)(b0 + r) * NCLS);
        orow[lane * 2]     = ea;
        orow[lane * 2 + 1] = eb;
    }
}

// ---------------------------------------------------------------------------
extern "C" void kernel_launch(void* const* d_in, const int* in_sizes, int n_in,
                              void* d_out, int out_size) {
    const float* x       = (const float*)d_in[0];
    const float* centers = (const float*)d_in[1];
    const float* Droot   = (const float*)d_in[2];
    float*       out     = (float*)d_out;

    prep_kernel<<<NCLS, NDIM>>>(centers, Droot);
    gmm_kernel<<<4096 / MB, 256>>>(x, out);
}

// round 3
// speedup vs baseline: 3.7926x; 3.7926x over previous
#include <cuda_runtime.h>
#include <math.h>

#define NCLS 256
#define NDIM 256
#define MB   32     // batch rows per block
#define NTHR 512

// Scratch (allocation-free rule: __device__ globals)
__device__ __align__(16) float g_dinvn[NCLS * NDIM];  // -0.5 / D  [k][d]  (negated!)
__device__ __align__(16) float g_cd[NCLS * NDIM];     //  c / D    [k][d]
__device__ __align__(16) float g_bias[NCLS];          // -0.5*(sum c^2/D + sum log D)

// ---------------------------------------------------------------------------
// Prep: one block per class k, 256 threads (one per dim)
// ---------------------------------------------------------------------------
__global__ void prep_kernel(const float* __restrict__ centers,
                            const float* __restrict__ Droot) {
    int k = blockIdx.x;
    int d = threadIdx.x;
    int idx = k * NDIM + d;

    float D    = fabsf(Droot[idx]) + 1e-4f;
    float dinv = 1.0f / D;
    float c    = centers[idx];

    g_dinvn[idx] = -0.5f * dinv;
    g_cd[idx]    = c * dinv;

    float p = c * c * dinv + logf(D);

    __shared__ float red[8];
    #pragma unroll
    for (int o = 16; o; o >>= 1) p += __shfl_xor_sync(0xFFFFFFFFu, p, o);
    if ((threadIdx.x & 31) == 0) red[threadIdx.x >> 5] = p;
    __syncthreads();
    if (threadIdx.x < 8) {
        float v = red[threadIdx.x];
        #pragma unroll
        for (int o = 4; o; o >>= 1) v += __shfl_xor_sync(0xFFu, v, o);
        if (threadIdx.x == 0) g_bias[k] = -0.5f * v;
    }
}

// ---------------------------------------------------------------------------
// Main: block = 32 rows x 256 classes, 512 threads.
// lane[2:0]=mg (row group), lane[4:3]=ksub, kkg = wid*4+ksub (64 class groups).
// Thread owns rows {mg, mg+8, mg+16, mg+24}, classes {kkg*4 .. kkg*4+3}.
// logit = sum_d x*(cd + dinvn*x) + bias[k];  resp = softmax_k(logit)
// x tile XOR-swizzled at 16B granularity: chunk' = chunk ^ (row & 7).
// ---------------------------------------------------------------------------
__global__ __launch_bounds__(NTHR, 1)
void gmm_kernel(const float* __restrict__ x, float* __restrict__ out) {
    __shared__ __align__(16) float xs[MB * NDIM];  // 32KB; reused for logits

    const int t  = threadIdx.x;
    const int b0 = blockIdx.x * MB;

    // Cooperative swizzled load of x tile
    {
        const float4* xg  = (const float4*)(x + (size_t)b0 * NDIM);
        float4*       xsv = (float4*)xs;
        #pragma unroll
        for (int i = t; i < MB * (NDIM / 4); i += NTHR) {
            int row = i >> 6;
            int c4  = i & 63;
            xsv[(row << 6) | (c4 ^ (row & 7))] = xg[i];
        }
    }
    __syncthreads();

    const int lane = t & 31;
    const int wid  = t >> 5;
    const int mg   = lane & 7;                  // row group 0..7
    const int kkg  = (wid << 2) | (lane >> 3);  // class group 0..63

    float acc[4][4];
    #pragma unroll
    for (int m = 0; m < 4; m++)
        #pragma unroll
        for (int kx = 0; kx < 4; kx++) acc[m][kx] = 0.0f;

    const float* dhb = g_dinvn + (kkg << 10);  // kkg*4*256
    const float* cdb = g_cd    + (kkg << 10);

    #pragma unroll 4
    for (int d4 = 0; d4 < NDIM / 4; d4++) {
        const int sc = (d4 ^ mg) << 2;
        float4 xv[4];
        #pragma unroll
        for (int m = 0; m < 4; m++)
            xv[m] = *(const float4*)(xs + (((mg + 8 * m) << 8) | sc));

        const int d = d4 << 2;
        #pragma unroll
        for (int kx = 0; kx < 4; kx++) {
            float4 dh = *(const float4*)(dhb + ((kx << 8) | d));
            float4 cd = *(const float4*)(cdb + ((kx << 8) | d));
            #pragma unroll
            for (int m = 0; m < 4; m++) {
                float a = acc[m][kx];
                float t0 = fmaf(xv[m].x, dh.x, cd.x);
                a = fmaf(xv[m].x, t0, a);
                float t1 = fmaf(xv[m].y, dh.y, cd.y);
                a = fmaf(xv[m].y, t1, a);
                float t2 = fmaf(xv[m].z, dh.z, cd.z);
                a = fmaf(xv[m].z, t2, a);
                float t3 = fmaf(xv[m].w, dh.w, cd.w);
                a = fmaf(xv[m].w, t3, a);
                acc[m][kx] = a;
            }
        }
    }

    __syncthreads();  // all reads of xs complete; reuse xs as swizzled logits

    {
        float4 bias = *(const float4*)(g_bias + (kkg << 2));
        #pragma unroll
        for (int m = 0; m < 4; m++) {
            int row = mg + 8 * m;
            float4 lv;
            lv.x = acc[m][0] + bias.x;
            lv.y = acc[m][1] + bias.y;
            lv.z = acc[m][2] + bias.z;
            lv.w = acc[m][3] + bias.w;
            // swizzled store: logical chunk kkg -> physical kkg ^ (row&7) = kkg ^ mg
            *(float4*)(xs + ((row << 8) | ((kkg ^ mg) << 2))) = lv;
        }
    }
    __syncthreads();

    // Softmax: warp w handles rows 2w, 2w+1; lane owns 8 classes (2 chunks).
    #pragma unroll
    for (int rr = 0; rr < 2; rr++) {
        int r = wid * 2 + rr;
        int s = r & 7;
        const float4* lrow = (const float4*)(xs + (r << 8));
        // logical chunks lane*2, lane*2+1 live at physical (chunk ^ s)
        float4 a = lrow[(lane * 2) ^ s];
        float4 b = lrow[(lane * 2 + 1) ^ s];

        float mx = fmaxf(fmaxf(fmaxf(a.x, a.y), fmaxf(a.z, a.w)),
                         fmaxf(fmaxf(b.x, b.y), fmaxf(b.z, b.w)));
        #pragma unroll
        for (int o = 16; o; o >>= 1) mx = fmaxf(mx, __shfl_xor_sync(0xFFFFFFFFu, mx, o));

        float4 ea, eb;
        ea.x = __expf(a.x - mx); ea.y = __expf(a.y - mx);
        ea.z = __expf(a.z - mx); ea.w = __expf(a.w - mx);
        eb.x = __expf(b.x - mx); eb.y = __expf(b.y - mx);
        eb.z = __expf(b.z - mx); eb.w = __expf(b.w - mx);

        float sum = (ea.x + ea.y) + (ea.z + ea.w) + (eb.x + eb.y) + (eb.z + eb.w);
        #pragma unroll
        for (int o = 16; o; o >>= 1) sum += __shfl_xor_sync(0xFFFFFFFFu, sum, o);

        float inv = 1.0f / sum;
        ea.x *= inv; ea.y *= inv; ea.z *= inv; ea.w *= inv;
        eb.x *= inv; eb.y *= inv; eb.z *= inv; eb.w *= inv;

        // Global store uses LOGICAL chunk indices (no swizzle in gmem!)
        float4* orow = (float4*)(out + (size_t)(b0 + r) * NCLS);
        orow[lane * 2]     = ea;
        orow[lane * 2 + 1] = eb;
    }
}

// ---------------------------------------------------------------------------
extern "C" void kernel_launch(void* const* d_in, const int* in_sizes, int n_in,
                              void* d_out, int out_size) {
    const float* x       = (const float*)d_in[0];
    const float* centers = (const float*)d_in[1];
    const float* Droot   = (const float*)d_in[2];
    float*       out     = (float*)d_out;

    prep_kernel<<<NCLS, NDIM>>>(centers, Droot);
    gmm_kernel<<<4096 / MB, NTHR>>>(x, out);
}

// round 4
// speedup vs baseline: 3.8398x; 1.0124x over previous
#include <cuda_runtime.h>
#include <math.h>

#define NCLS   256
#define NDIM   256
#define MB     32     // batch rows per block
#define NTHR   512
#define DSTAGE 16     // dims per stage
#define NSTAGE (NDIM / DSTAGE)

// smem map (dynamic, 96KB):
//   [0      , 32KB) : x tile (32 rows x 256 f32, 16B-swizzled); reused for logits
//   [32KB   , 64KB) : class stage buffer 0
//   [64KB   , 96KB) : class stage buffer 1
// class stage layout: per class k (0..255): 8 chunks of 16B
//   chunks 0-3 = dinvn dims [s*16 .. s*16+16), chunks 4-7 = cd same dims
//   chunk swizzle: physical = chunk ^ ((k>>2) & 3)
#define SMEM_BYTES (32768 * 3)

__device__ __align__(16) float g_dinvn[NCLS * NDIM];  // -0.5 / D
__device__ __align__(16) float g_cd[NCLS * NDIM];     //  c / D
__device__ __align__(16) float g_bias[NCLS];

// ---------------------------------------------------------------------------
__device__ __forceinline__ void ffma2(unsigned long long& d, unsigned long long a,
                                      unsigned long long b, unsigned long long c) {
    asm("fma.rn.f32x2 %0, %1, %2, %3;" : "=l"(d) : "l"(a), "l"(b), "l"(c));
}

__device__ __forceinline__ void cpasync16(void* dst, const void* src) {
    unsigned d = (unsigned)__cvta_generic_to_shared(dst);
    asm volatile("cp.async.cg.shared.global [%0], [%1], 16;" :: "r"(d), "l"(src));
}

// ---------------------------------------------------------------------------
__global__ void prep_kernel(const float* __restrict__ centers,
                            const float* __restrict__ Droot) {
    int k = blockIdx.x;
    int d = threadIdx.x;
    int idx = k * NDIM + d;

    float D    = fabsf(Droot[idx]) + 1e-4f;
    float dinv = 1.0f / D;
    float c    = centers[idx];

    g_dinvn[idx] = -0.5f * dinv;
    g_cd[idx]    = c * dinv;

    float p = c * c * dinv + logf(D);

    __shared__ float red[8];
    #pragma unroll
    for (int o = 16; o; o >>= 1) p += __shfl_xor_sync(0xFFFFFFFFu, p, o);
    if ((threadIdx.x & 31) == 0) red[threadIdx.x >> 5] = p;
    __syncthreads();
    if (threadIdx.x < 8) {
        float v = red[threadIdx.x];
        #pragma unroll
        for (int o = 4; o; o >>= 1) v += __shfl_xor_sync(0xFFu, v, o);
        if (threadIdx.x == 0) g_bias[k] = -0.5f * v;
    }
}

// ---------------------------------------------------------------------------
// Thread (mg = lane&7, kkg = (wid<<2)|(lane>>3)) owns rows {mg+8m}, classes
// {kkg*4..+3}.  logit = sum_d x*(cd + dinvn*x) + bias; resp = softmax_k.
// ---------------------------------------------------------------------------
__global__ __launch_bounds__(NTHR, 1)
void gmm_kernel(const float* __restrict__ x, float* __restrict__ out) {
    extern __shared__ __align__(16) unsigned char smem_raw[];
    float* xs = (float*)smem_raw;

    const int t  = threadIdx.x;
    const int b0 = blockIdx.x * MB;

    // ---- stage-fill helper state (uniform per thread) ----
    const int fch = t & 7;  // which 16B chunk of a class row this thread fills
    const float* fsrc = (fch < 4) ? (g_dinvn + fch * 4) : (g_cd + (fch - 4) * 4);

    // prefetch class stage 0 into buffer 0
    {
        unsigned char* buf = smem_raw + 32768;
        #pragma unroll
        for (int j = 0; j < 4; j++) {
            int k = (t >> 3) + 64 * j;
            int chsw = fch ^ ((k >> 2) & 3);
            cpasync16(buf + (size_t)(k * 8 + chsw) * 16, fsrc + k * NDIM);
        }
        asm volatile("cp.async.commit_group;");
    }

    // cooperative swizzled load of x tile
    {
        const float4* xg  = (const float4*)(x + (size_t)b0 * NDIM);
        float4*       xsv = (float4*)xs;
        #pragma unroll
        for (int i = t; i < MB * (NDIM / 4); i += NTHR) {
            int row = i >> 6;
            int c4  = i & 63;
            xsv[(row << 6) | (c4 ^ (row & 7))] = xg[i];
        }
    }

    const int lane = t & 31;
    const int wid  = t >> 5;
    const int mg   = lane & 7;                  // row group 0..7
    const int kkg  = (wid << 2) | (lane >> 3);  // class group 0..63
    const int kswz = kkg & 3;

    unsigned long long acc[4][4];
    #pragma unroll
    for (int m = 0; m < 4; m++)
        #pragma unroll
        for (int kx = 0; kx < 4; kx++) acc[m][kx] = 0ull;

    for (int s = 0; s < NSTAGE; s++) {
        // prefetch next stage into the other buffer
        if (s + 1 < NSTAGE) {
            unsigned char* buf = smem_raw + 32768 + ((s + 1) & 1) * 32768;
            const float* srcs = fsrc + (s + 1) * DSTAGE;
            #pragma unroll
            for (int j = 0; j < 4; j++) {
                int k = (t >> 3) + 64 * j;
                int chsw = fch ^ ((k >> 2) & 3);
                cpasync16(buf + (size_t)(k * 8 + chsw) * 16, srcs + k * NDIM);
            }
            asm volatile("cp.async.commit_group;");
            asm volatile("cp.async.wait_group 1;");
        } else {
            asm volatile("cp.async.wait_group 0;");
        }
        __syncthreads();  // stage s visible to all (also covers x tile at s=0)

        const unsigned char* cb = smem_raw + 32768 + (s & 1) * 32768;

        #pragma unroll
        for (int d4l = 0; d4l < 4; d4l++) {
            const int gchunk = s * 4 + d4l;
            ulonglong2 xv[4];
            #pragma unroll
            for (int m = 0; m < 4; m++)
                xv[m] = *(const ulonglong2*)(xs + (((mg + 8 * m) << 8) |
                                                  ((gchunk ^ mg) << 2)));
            const int sw = d4l ^ kswz;
            #pragma unroll
            for (int kx = 0; kx < 4; kx++) {
                const unsigned char* kb = cb + (size_t)(((kkg << 2) | kx) << 7);
                ulonglong2 dh = *(const ulonglong2*)(kb + sw * 16);
                ulonglong2 cd = *(const ulonglong2*)(kb + (sw + 4) * 16);
                #pragma unroll
                for (int m = 0; m < 4; m++) {
                    unsigned long long t0, t1;
                    ffma2(t0, xv[m].x, dh.x, cd.x);
                    ffma2(acc[m][kx], xv[m].x, t0, acc[m][kx]);
                    ffma2(t1, xv[m].y, dh.y, cd.y);
                    ffma2(acc[m][kx], xv[m].y, t1, acc[m][kx]);
                }
            }
        }
        __syncthreads();  // all reads of buf (s&1) done before refill at s+1
    }

    // ---- logits into xs (swizzled), then softmax ----
    {
        float4 bias = *(const float4*)(g_bias + (kkg << 2));
        #pragma unroll
        for (int m = 0; m < 4; m++) {
            int row = mg + 8 * m;
            float2 a0 = *reinterpret_cast<float2*>(&acc[m][0]);
            float2 a1 = *reinterpret_cast<float2*>(&acc[m][1]);
            float2 a2 = *reinterpret_cast<float2*>(&acc[m][2]);
            float2 a3 = *reinterpret_cast<float2*>(&acc[m][3]);
            float4 lv;
            lv.x = a0.x + a0.y + bias.x;
            lv.y = a1.x + a1.y + bias.y;
            lv.z = a2.x + a2.y + bias.z;
            lv.w = a3.x + a3.y + bias.w;
            *(float4*)(xs + ((row << 8) | ((kkg ^ mg) << 2))) = lv;
        }
    }
    __syncthreads();

    #pragma unroll
    for (int rr = 0; rr < 2; rr++) {
        int r = wid * 2 + rr;
        int s = r & 7;
        const float4* lrow = (const float4*)(xs + (r << 8));
        float4 a = lrow[(lane * 2) ^ s];
        float4 b = lrow[(lane * 2 + 1) ^ s];

        float mx = fmaxf(fmaxf(fmaxf(a.x, a.y), fmaxf(a.z, a.w)),
                         fmaxf(fmaxf(b.x, b.y), fmaxf(b.z, b.w)));
        #pragma unroll
        for (int o = 16; o; o >>= 1) mx = fmaxf(mx, __shfl_xor_sync(0xFFFFFFFFu, mx, o));

        float4 ea, eb;
        ea.x = __expf(a.x - mx); ea.y = __expf(a.y - mx);
        ea.z = __expf(a.z - mx); ea.w = __expf(a.w - mx);
        eb.x = __expf(b.x - mx); eb.y = __expf(b.y - mx);
        eb.z = __expf(b.z - mx); eb.w = __expf(b.w - mx);

        float sum = (ea.x + ea.y) + (ea.z + ea.w) + (eb.x + eb.y) + (eb.z + eb.w);
        #pragma unroll
        for (int o = 16; o; o >>= 1) sum += __shfl_xor_sync(0xFFFFFFFFu, sum, o);

        float inv = 1.0f / sum;
        ea.x *= inv; ea.y *= inv; ea.z *= inv; ea.w *= inv;
        eb.x *= inv; eb.y *= inv; eb.z *= inv; eb.w *= inv;

        float4* orow = (float4*)(out + (size_t)(b0 + r) * NCLS);
        orow[lane * 2]     = ea;   // logical chunk indices in gmem
        orow[lane * 2 + 1] = eb;
    }
}

// ---------------------------------------------------------------------------
extern "C" void kernel_launch(void* const* d_in, const int* in_sizes, int n_in,
                              void* d_out, int out_size) {
    const float* x       = (const float*)d_in[0];
    const float* centers = (const float*)d_in[1];
    const float* Droot   = (const float*)d_in[2];
    float*       out     = (float*)d_out;

    cudaFuncSetAttribute(gmm_kernel, cudaFuncAttributeMaxDynamicSharedMemorySize,
                         SMEM_BYTES);

    prep_kernel<<<NCLS, NDIM>>>(centers, Droot);
    gmm_kernel<<<4096 / MB, NTHR, SMEM_BYTES>>>(x, out);
}

// round 7
// speedup vs baseline: 5.7485x; 1.4971x over previous
#include <cuda_runtime.h>
#include <cuda_fp16.h>
#include <cstdint>
#include <math.h>

#define BATCH 4096
#define NCLS  256
#define NDIM  256
#define KPHI  1536            // [hi(512) | lo(512) | hi(512)]

#define MT 128                // CTA M tile
#define NT 64                 // CTA N tile
#define KSTAGE 64             // halves per k-stage
#define NSTAGES (KPHI / KSTAGE)   // 24
#define NBUF 4
#define A_BYTES (MT * KSTAGE * 2)            // 16KB
#define B_BYTES (NT * KSTAGE * 2)            // 8KB
#define STAGE_BYTES (A_BYTES + B_BYTES)      // 24KB
#define SMEM_TOTAL (NBUF * STAGE_BYTES)      // 96KB

__device__ __align__(16) __half g_phi[BATCH * KPHI];   // 12MB
__device__ __align__(16) __half g_w[NCLS * KPHI];      // 768KB
__device__ __align__(16) float  g_bias[NCLS];
__device__ __align__(16) float  g_logits[BATCH * NCLS];

// ---------------------------------------------------------------------------
__device__ __forceinline__ unsigned smem_u32(const void* p) {
    return (unsigned)__cvta_generic_to_shared(p);
}

#define LDSM_X4(r0, r1, r2, r3, addr) \
    asm volatile("ldmatrix.sync.aligned.m8n8.x4.shared.b16 {%0,%1,%2,%3}, [%4];" \
                 : "=r"(r0), "=r"(r1), "=r"(r2), "=r"(r3) : "r"(addr))

#define MMA16816(d, a0, a1, a2, a3, b0, b1) \
    asm volatile("mma.sync.aligned.m16n8k16.row.col.f32.f16.f16.f32 " \
                 "{%0,%1,%2,%3}, {%4,%5,%6,%7}, {%8,%9}, {%0,%1,%2,%3};" \
                 : "+f"((d)[0]), "+f"((d)[1]), "+f"((d)[2]), "+f"((d)[3]) \
                 : "r"(a0), "r"(a1), "r"(a2), "r"(a3), "r"(b0), "r"(b1))

// ---------------------------------------------------------------------------
// prep_x: one block per batch row (128 threads, 2 dims each)
// phi row: [0:256)=x2_hi [256:512)=x_hi [512:768)=x2_lo [768:1024)=x_lo
//          [1024:1280)=x2_hi [1280:1536)=x_hi
// ---------------------------------------------------------------------------
__global__ void prep_x_kernel(const float* __restrict__ x) {
    int b  = blockIdx.x;
    int d0 = threadIdx.x * 2;
    float2 xv = *(const float2*)(x + (size_t)b * NDIM + d0);
    __half* row = g_phi + (size_t)b * KPHI;

    float a0 = xv.x * xv.x, a1 = xv.y * xv.y;
    __half h0 = __float2half_rn(a0), h1 = __float2half_rn(a1);
    __half l0 = __float2half_rn(a0 - __half2float(h0));
    __half l1 = __float2half_rn(a1 - __half2float(h1));
    __half2 x2h = __halves2half2(h0, h1);
    *(__half2*)(row + d0)        = x2h;
    *(__half2*)(row + 512 + d0)  = __halves2half2(l0, l1);
    *(__half2*)(row + 1024 + d0) = x2h;

    __half p0 = __float2half_rn(xv.x), p1 = __float2half_rn(xv.y);
    __half q0 = __float2half_rn(xv.x - __half2float(p0));
    __half q1 = __float2half_rn(xv.y - __half2float(p1));
    __half2 xh = __halves2half2(p0, p1);
    *(__half2*)(row + 256 + d0)  = xh;
    *(__half2*)(row + 768 + d0)  = __halves2half2(q0, q1);
    *(__half2*)(row + 1280 + d0) = xh;
}

// ---------------------------------------------------------------------------
// prep_w: one block per class. W row: [0:256)=w1_hi [256:512)=w2_hi
//         [512:768)=w1_hi [768:1024)=w2_hi [1024:1280)=w1_lo [1280:1536)=w2_lo
// ---------------------------------------------------------------------------
__global__ void prep_w_kernel(const float* __restrict__ centers,
                              const float* __restrict__ Droot) {
    int k = blockIdx.x;
    int d = threadIdx.x;
    int idx = k * NDIM + d;

    float D    = fabsf(Droot[idx]) + 1e-4f;
    float dinv = 1.0f / D;
    float c    = centers[idx];

    float w1 = -0.5f * dinv;
    float w2 = c * dinv;
    __half w1h = __float2half_rn(w1);
    __half w1l = __float2half_rn(w1 - __half2float(w1h));
    __half w2h = __float2half_rn(w2);
    __half w2l = __float2half_rn(w2 - __half2float(w2h));

    __half* row = g_w + (size_t)k * KPHI;
    row[d]        = w1h;
    row[256 + d]  = w2h;
    row[512 + d]  = w1h;
    row[768 + d]  = w2h;
    row[1024 + d] = w1l;
    row[1280 + d] = w2l;

    float p = c * c * dinv + logf(D);
    __shared__ float red[8];
    #pragma unroll
    for (int o = 16; o; o >>= 1) p += __shfl_xor_sync(0xFFFFFFFFu, p, o);
    if ((threadIdx.x & 31) == 0) red[threadIdx.x >> 5] = p;
    __syncthreads();
    if (threadIdx.x < 8) {
        float v = red[threadIdx.x];
        #pragma unroll
        for (int o = 4; o; o >>= 1) v += __shfl_xor_sync(0xFFu, v, o);
        if (threadIdx.x == 0) g_bias[k] = -0.5f * v;
    }
}

// ---------------------------------------------------------------------------
// GEMM: 128 CTAs (32 M x 4 N), 256 threads. CTA tile 128x64, warp tile 32x32.
// Smem rows are 64 halves (128B) with 16B XOR swizzle: chunk' = chunk ^ (row&7).
// ---------------------------------------------------------------------------
__device__ __forceinline__ void issue_stage(unsigned char* sm, int t,
                                            int m0, int n0, int s) {
    const int koff = s * KSTAGE;
    unsigned abase = smem_u32(sm + (s % NBUF) * STAGE_BYTES);
    unsigned bbase = abase + A_BYTES;
    #pragma unroll
    for (int i = 0; i < 6; i++) {
        int idx = t + (i << 8);
        unsigned dst;
        const __half* src;
        if (idx < 1024) {                      // A: 128 rows x 8 chunks
            int r = idx >> 3, j = idx & 7;
            dst = abase + r * 128 + ((unsigned)(j ^ (r & 7)) << 4);
            src = g_phi + (size_t)(m0 + r) * KPHI + koff + j * 8;
        } else {                               // B: 64 rows x 8 chunks
            int x = idx - 1024;
            int r = x >> 3, j = x & 7;
            dst = bbase + r * 128 + ((unsigned)(j ^ (r & 7)) << 4);
            src = g_w + (size_t)(n0 + r) * KPHI + koff + j * 8;
        }
        asm volatile("cp.async.cg.shared.global [%0], [%1], 16;" :: "r"(dst), "l"(src));
    }
    asm volatile("cp.async.commit_group;");
}

__global__ __launch_bounds__(256, 1) void gemm_kernel() {
    extern __shared__ __align__(128) unsigned char sm[];
    const int t    = threadIdx.x;
    const int lane = t & 31;
    const int wid  = t >> 5;
    const int wm   = wid & 3;        // warp m index (0..3)
    const int wn   = wid >> 2;       // warp n index (0..1)
    const int m0   = (blockIdx.x >> 2) * MT;
    const int n0   = (blockIdx.x & 3) * NT;

    float d[2][4][4];
    #pragma unroll
    for (int mt = 0; mt < 2; mt++)
        #pragma unroll
        for (int nt = 0; nt < 4; nt++)
            #pragma unroll
            for (int e = 0; e < 4; e++) d[mt][nt][e] = 0.0f;

    issue_stage(sm, t, m0, n0, 0);
    issue_stage(sm, t, m0, n0, 1);
    issue_stage(sm, t, m0, n0, 2);

    // per-lane ldmatrix row/chunk components (stage-invariant)
    const int arow  = wm * 32 + (lane & 15);           // + mt*16
    const int akh   = lane >> 4;                        // k-half (chunk lsb)
    const int brow  = wn * 32 + (lane & 7) + ((lane >> 4) & 1) * 8;  // + np*16
    const int bkh   = (lane >> 3) & 1;

    for (int s = 0; s < NSTAGES; s++) {
        if (s <= NSTAGES - 3)      asm volatile("cp.async.wait_group 2;");
        else if (s == NSTAGES - 2) asm volatile("cp.async.wait_group 1;");
        else                       asm volatile("cp.async.wait_group 0;");
        __syncthreads();

        unsigned abase = smem_u32(sm + (s % NBUF) * STAGE_BYTES);
        unsigned bbase = abase + A_BYTES;

        #pragma unroll
        for (int ks = 0; ks < 4; ks++) {
            unsigned a[2][4], b[2][4];
            #pragma unroll
            for (int mt = 0; mt < 2; mt++) {
                int r  = arow + mt * 16;
                int kc = ks * 2 + akh;
                unsigned addr = abase + r * 128 + ((unsigned)(kc ^ (r & 7)) << 4);
                LDSM_X4(a[mt][0], a[mt][1], a[mt][2], a[mt][3], addr);
            }
            #pragma unroll
            for (int np = 0; np < 2; np++) {
                int r  = brow + np * 16;
                int kc = ks * 2 + bkh;
                unsigned addr = bbase + r * 128 + ((unsigned)(kc ^ (r & 7)) << 4);
                LDSM_X4(b[np][0], b[np][1], b[np][2], b[np][3], addr);
            }
            #pragma unroll
            for (int mt = 0; mt < 2; mt++)
                #pragma unroll
                for (int nt = 0; nt < 4; nt++) {
                    int np = nt >> 1, off = (nt & 1) * 2;
                    MMA16816(d[mt][nt], a[mt][0], a[mt][1], a[mt][2], a[mt][3],
                             b[np][off], b[np][off + 1]);
                }
        }
        __syncthreads();
        if (s + 3 < NSTAGES) issue_stage(sm, t, m0, n0, s + 3);
    }

    // epilogue: c-frag -> g_logits (+bias)
    #pragma unroll
    for (int mt = 0; mt < 2; mt++) {
        int row = m0 + wm * 32 + mt * 16 + (lane >> 2);
        #pragma unroll
        for (int nt = 0; nt < 4; nt++) {
            int col = n0 + wn * 32 + nt * 8 + (lane & 3) * 2;
            float2 bv = *(const float2*)(g_bias + col);
            float2 v0, v1;
            v0.x = d[mt][nt][0] + bv.x;
            v0.y = d[mt][nt][1] + bv.y;
            v1.x = d[mt][nt][2] + bv.x;
            v1.y = d[mt][nt][3] + bv.y;
            *(float2*)(g_logits + (size_t)row * NCLS + col)       = v0;
            *(float2*)(g_logits + (size_t)(row + 8) * NCLS + col) = v1;
        }
    }
}

// ---------------------------------------------------------------------------
// Softmax: warp per row, 8 rows per 256-thread block.
// ---------------------------------------------------------------------------
__global__ __launch_bounds__(256) void softmax_kernel(float* __restrict__ out) {
    const int lane = threadIdx.x & 31;
    const int wid  = threadIdx.x >> 5;
    const int r    = blockIdx.x * 8 + wid;

    const float4* lrow = (const float4*)(g_logits + (size_t)r * NCLS);
    float4 a = lrow[lane * 2];
    float4 b = lrow[lane * 2 + 1];

    float mx = fmaxf(fmaxf(fmaxf(a.x, a.y), fmaxf(a.z, a.w)),
                     fmaxf(fmaxf(b.x, b.y), fmaxf(b.z, b.w)));
    #pragma unroll
    for (int o = 16; o; o >>= 1) mx = fmaxf(mx, __shfl_xor_sync(0xFFFFFFFFu, mx, o));

    float4 ea, eb;
    ea.x = __expf(a.x - mx); ea.y = __expf(a.y - mx);
    ea.z = __expf(a.z - mx); ea.w = __expf(a.w - mx);
    eb.x = __expf(b.x - mx); eb.y = __expf(b.y - mx);
    eb.z = __expf(b.z - mx); eb.w = __expf(b.w - mx);

    float sum = (ea.x + ea.y) + (ea.z + ea.w) + (eb.x + eb.y) + (eb.z + eb.w);
    #pragma unroll
    for (int o = 16; o; o >>= 1) sum += __shfl_xor_sync(0xFFFFFFFFu, sum, o);

    float inv = 1.0f / sum;
    ea.x *= inv; ea.y *= inv; ea.z *= inv; ea.w *= inv;
    eb.x *= inv; eb.y *= inv; eb.z *= inv; eb.w *= inv;

    float4* orow = (float4*)(out + (size_t)r * NCLS);
    orow[lane * 2]     = ea;
    orow[lane * 2 + 1] = eb;
}

// ---------------------------------------------------------------------------
extern "C" void kernel_launch(void* const* d_in, const int* in_sizes, int n_in,
                              void* d_out, int out_size) {
    const float* x       = (const float*)d_in[0];
    const float* centers = (const float*)d_in[1];
    const float* Droot   = (const float*)d_in[2];
    float*       out     = (float*)d_out;

    cudaFuncSetAttribute(gemm_kernel, cudaFuncAttributeMaxDynamicSharedMemorySize,
                         SMEM_TOTAL);

    prep_x_kernel<<<BATCH, 128>>>(x);
    prep_w_kernel<<<NCLS, NDIM>>>(centers, Droot);
    gemm_kernel<<<(BATCH / MT) * (NCLS / NT), 256, SMEM_TOTAL>>>();
    softmax_kernel<<<BATCH / 8, 256>>>(out);
}

// round 9
// speedup vs baseline: 5.9280x; 1.0312x over previous
#include <cuda_runtime.h>
#include <cuda_fp16.h>
#include <cstdint>
#include <math.h>

#define BATCH 4096
#define NCLS  256
#define NDIM  256

#define MT 32                  // batch rows per CTA
#define NSTAGES 24             // logical K stages of 64 halves
#define NBUF 4
#define B_BYTES 32768          // 256 classes x 64 halves
#define A_OFF   (NBUF * B_BYTES)          // 131072
#define A_BYTES (MT * 1024 * 2)           // 64KB  (phys K=1024 per row)
#define SMEM_TOTAL (A_OFF + A_BYTES)      // 192KB

// W phys layout per class row (K=1024): [w1_hi|w2_hi|w1_lo|w2_lo] (256 each)
__device__ __align__(16) __half g_w[NCLS * 1024];      // 512KB
__device__ __align__(16) float  g_bias[NCLS];

// ---------------------------------------------------------------------------
__device__ __forceinline__ unsigned smem_u32(const void* p) {
    return (unsigned)__cvta_generic_to_shared(p);
}
__device__ __forceinline__ unsigned pack2(__half lo, __half hi) {
    return (unsigned)__half_as_ushort(lo) | ((unsigned)__half_as_ushort(hi) << 16);
}

#define LDSM_X4(r0, r1, r2, r3, addr) \
    asm volatile("ldmatrix.sync.aligned.m8n8.x4.shared.b16 {%0,%1,%2,%3}, [%4];" \
                 : "=r"(r0), "=r"(r1), "=r"(r2), "=r"(r3) : "r"(addr))

#define MMA16816(d, a0, a1, a2, a3, b0, b1) \
    asm volatile("mma.sync.aligned.m16n8k16.row.col.f32.f16.f16.f32 " \
                 "{%0,%1,%2,%3}, {%4,%5,%6,%7}, {%8,%9}, {%0,%1,%2,%3};" \
                 : "+f"((d)[0]), "+f"((d)[1]), "+f"((d)[2]), "+f"((d)[3]) \
                 : "r"(a0), "r"(a1), "r"(a2), "r"(a3), "r"(b0), "r"(b1))

// ---------------------------------------------------------------------------
// prep_w: one block per class; phys K=1024 layout + bias
// ---------------------------------------------------------------------------
__global__ void prep_w_kernel(const float* __restrict__ centers,
                              const float* __restrict__ Droot) {
    int k = blockIdx.x;
    int d = threadIdx.x;
    int idx = k * NDIM + d;

    float D    = fabsf(Droot[idx]) + 1e-4f;
    float dinv = 1.0f / D;
    float c    = centers[idx];

    float w1 = -0.5f * dinv;
    float w2 = c * dinv;
    __half w1h = __float2half_rn(w1);
    __half w1l = __float2half_rn(w1 - __half2float(w1h));
    __half w2h = __float2half_rn(w2);
    __half w2l = __float2half_rn(w2 - __half2float(w2h));

    __half* row = g_w + (size_t)k * 1024;
    row[d]       = w1h;
    row[256 + d] = w2h;
    row[512 + d] = w1l;
    row[768 + d] = w2l;

    float p = c * c * dinv + logf(D);
    __shared__ float red[8];
    #pragma unroll
    for (int o = 16; o; o >>= 1) p += __shfl_xor_sync(0xFFFFFFFFu, p, o);
    if ((threadIdx.x & 31) == 0) red[threadIdx.x >> 5] = p;
    __syncthreads();
    if (threadIdx.x < 8) {
        float v = red[threadIdx.x];
        #pragma unroll
        for (int o = 4; o; o >>= 1) v += __shfl_xor_sync(0xFFu, v, o);
        if (threadIdx.x == 0) g_bias[k] = -0.5f * v;
    }
}

// ---------------------------------------------------------------------------
// Logical stage s -> phys stage (of 64 halves):
//   A (phi): s<8 -> s (hi);  8<=s<16 -> s (lo at 8..15);  s>=16 -> s-16 (hi)
//   B (W):   s<8 -> s (hi);  8<=s<16 -> s-8 (hi);         s>=16 -> s-8 (lo)
// phi phys row layout (K=1024): [x2_hi(256) | x_hi(256) | x2_lo(256) | x_lo(256)]
// W   phys row layout (K=1024): [w1_hi | w2_hi | w1_lo | w2_lo]
// ---------------------------------------------------------------------------
__device__ __forceinline__ int a_phys(int s) { return s < 16 ? s : s - 16; }
__device__ __forceinline__ int b_phys(int s) {
    if (s < 8) return s;
    if (s < 16) return s - 8;
    return s - 8;   // 16..23 -> 8..15 (lo half)
}

__device__ __forceinline__ void issue_b_stage(unsigned char* sm, int t, int s) {
    unsigned bbase = smem_u32(sm + (s % NBUF) * B_BYTES);
    const int bk = b_phys(s) * 64;
    const int j  = t & 7;
    #pragma unroll
    for (int i = 0; i < 8; i++) {
        int k = (t >> 3) + 32 * i;
        unsigned dst = bbase + k * 128 + ((unsigned)(j ^ (k & 7)) << 4);
        const __half* src = g_w + (size_t)k * 1024 + bk + j * 8;
        asm volatile("cp.async.cg.shared.global [%0], [%1], 16;" :: "r"(dst), "l"(src));
    }
    asm volatile("cp.async.commit_group;");
}

__global__ __launch_bounds__(256, 1) void gmm_fused_kernel(
        const float* __restrict__ x, float* __restrict__ out) {
    extern __shared__ __align__(128) unsigned char sm[];
    const int t    = threadIdx.x;
    const int lane = t & 31;
    const int wid  = t >> 5;
    const int b0   = blockIdx.x * MT;

    // ---- prologue: start B pipeline, then convert x -> phi in smem A ----
    issue_b_stage(sm, t, 0);
    issue_b_stage(sm, t, 1);
    issue_b_stage(sm, t, 2);

    {
        // thread: row r = t>>3, dims [seg*32, seg*32+32)
        const int r   = t >> 3;
        const int seg = t & 7;
        const float* xr = x + (size_t)(b0 + r) * NDIM + seg * 32;
        unsigned arow = smem_u32(sm + A_OFF) + r * 2048;
        const unsigned rs = (unsigned)(r & 7);
        #pragma unroll
        for (int c = 0; c < 4; c++) {
            float4 xa = *(const float4*)(xr + c * 8);
            float4 xb = *(const float4*)(xr + c * 8 + 4);
            float v[8] = {xa.x, xa.y, xa.z, xa.w, xb.x, xb.y, xb.z, xb.w};
            __half x2h[8], x2l[8], xh[8], xl[8];
            #pragma unroll
            for (int e = 0; e < 8; e++) {
                float a = v[e] * v[e];
                x2h[e] = __float2half_rn(a);
                x2l[e] = __float2half_rn(a - __half2float(x2h[e]));
                xh[e]  = __float2half_rn(v[e]);
                xl[e]  = __float2half_rn(v[e] - __half2float(xh[e]));
            }
            const int db = seg * 32 + c * 8;
            const __half* regs[4] = {x2h, xh, x2l, xl};
            #pragma unroll
            for (int Rg = 0; Rg < 4; Rg++) {
                int p0 = Rg * 256 + db;
                int ks = p0 >> 6;
                unsigned j = (unsigned)((p0 >> 3) & 7);
                unsigned addr = arow + ks * 128 + ((j ^ rs) << 4);
                const __half* h = regs[Rg];
                unsigned p0w = pack2(h[0], h[1]);
                unsigned p1w = pack2(h[2], h[3]);
                unsigned p2w = pack2(h[4], h[5]);
                unsigned p3w = pack2(h[6], h[7]);
                asm volatile("st.shared.v4.b32 [%0], {%1,%2,%3,%4};"
                             :: "r"(addr), "r"(p0w), "r"(p1w), "r"(p2w), "r"(p3w));
            }
        }
    }

    // ---- mainloop: warp tile 32x32 (warp wid owns cols wid*32..+31) ----
    float d[2][4][4];
    #pragma unroll
    for (int mt = 0; mt < 2; mt++)
        #pragma unroll
        for (int nt = 0; nt < 4; nt++)
            #pragma unroll
            for (int e = 0; e < 4; e++) d[mt][nt][e] = 0.0f;

    const unsigned abase0 = smem_u32(sm + A_OFF);
    const int arow = lane & 15;          // + mt*16
    const int akh  = lane >> 4;
    const int brow = wid * 32 + (lane & 7) + ((lane >> 4) & 1) * 8;  // + np*16
    const int bkh  = (lane >> 3) & 1;

    for (int s = 0; s < NSTAGES; s++) {
        if (s <= NSTAGES - 3)      asm volatile("cp.async.wait_group 2;");
        else if (s == NSTAGES - 2) asm volatile("cp.async.wait_group 1;");
        else                       asm volatile("cp.async.wait_group 0;");
        __syncthreads();   // stage s B ready; also covers A conversion at s=0

        unsigned bbase = smem_u32(sm + (s % NBUF) * B_BYTES);
        unsigned abase = abase0 + a_phys(s) * 128;

        #pragma unroll
        for (int ks = 0; ks < 4; ks++) {
            unsigned a[2][4], b[2][4];
            #pragma unroll
            for (int mt = 0; mt < 2; mt++) {
                int r = arow + mt * 16;
                unsigned addr = abase + r * 2048 +
                                ((unsigned)((ks * 2 + akh) ^ (r & 7)) << 4);
                LDSM_X4(a[mt][0], a[mt][1], a[mt][2], a[mt][3], addr);
            }
            #pragma unroll
            for (int np = 0; np < 2; np++) {
                int r = brow + np * 16;
                unsigned addr = bbase + r * 128 +
                                ((unsigned)((ks * 2 + bkh) ^ (r & 7)) << 4);
                LDSM_X4(b[np][0], b[np][1], b[np][2], b[np][3], addr);
            }
            #pragma unroll
            for (int mt = 0; mt < 2; mt++)
                #pragma unroll
                for (int nt = 0; nt < 4; nt++) {
                    int np = nt >> 1, off = (nt & 1) * 2;
                    MMA16816(d[mt][nt], a[mt][0], a[mt][1], a[mt][2], a[mt][3],
                             b[np][off], b[np][off + 1]);
                }
        }
        __syncthreads();
        if (s + 3 < NSTAGES) issue_b_stage(sm, t, s + 3);
    }

    // ---- epilogue: logits (+bias) into smem (reuse B buffers), softmax ----
    float* ls = (float*)sm;   // 32 rows x 256 cols f32 = 32KB
    __syncthreads();
    #pragma unroll
    for (int mt = 0; mt < 2; mt++) {
        int row = mt * 16 + (lane >> 2);
        #pragma unroll
        for (int nt = 0; nt < 4; nt++) {
            int col = wid * 32 + nt * 8 + (lane & 3) * 2;
            float2 bv = *(const float2*)(g_bias + col);
            float2 v0 = {d[mt][nt][0] + bv.x, d[mt][nt][1] + bv.y};
            float2 v1 = {d[mt][nt][2] + bv.x, d[mt][nt][3] + bv.y};
            *(float2*)(ls + row * NCLS + col)       = v0;
            *(float2*)(ls + (row + 8) * NCLS + col) = v1;
        }
    }
    __syncthreads();

    #pragma unroll
    for (int rr = 0; rr < 4; rr++) {
        int r = wid * 4 + rr;
        const float4* lrow = (const float4*)(ls + r * NCLS);
        float4 a = lrow[lane * 2];
        float4 b = lrow[lane * 2 + 1];

        float mx = fmaxf(fmaxf(fmaxf(a.x, a.y), fmaxf(a.z, a.w)),
                         fmaxf(fmaxf(b.x, b.y), fmaxf(b.z, b.w)));
        #pragma unroll
        for (int o = 16; o; o >>= 1) mx = fmaxf(mx, __shfl_xor_sync(0xFFFFFFFFu, mx, o));

        float4 ea, eb;
        ea.x = __expf(a.x - mx); ea.y = __expf(a.y - mx);
        ea.z = __expf(a.z - mx); ea.w = __expf(a.w - mx);
        eb.x = __expf(b.x - mx); eb.y = __expf(b.y - mx);
        eb.z = __expf(b.z - mx); eb.w = __expf(b.w - mx);

        float sum = (ea.x + ea.y) + (ea.z + ea.w) + (eb.x + eb.y) + (eb.z + eb.w);
        #pragma unroll
        for (int o = 16; o; o >>= 1) sum += __shfl_xor_sync(0xFFFFFFFFu, sum, o);

        float inv = 1.0f / sum;
        ea.x *= inv; ea.y *= inv; ea.z *= inv; ea.w *= inv;
        eb.x *= inv; eb.y *= inv; eb.z *= inv; eb.w *= inv;

        float4* orow = (float4*)(out + (size_t)(b0 + r) * NCLS);
        orow[lane * 2]     = ea;
        orow[lane * 2 + 1] = eb;
    }
}

// ---------------------------------------------------------------------------
extern "C" void kernel_launch(void* const* d_in, const int* in_sizes, int n_in,
                              void* d_out, int out_size) {
    const float* x       = (const float*)d_in[0];
    const float* centers = (const float*)d_in[1];
    const float* Droot   = (const float*)d_in[2];
    float*       out     = (float*)d_out;

    cudaFuncSetAttribute(gmm_fused_kernel,
                         cudaFuncAttributeMaxDynamicSharedMemorySize, SMEM_TOTAL);

    prep_w_kernel<<<NCLS, NDIM>>>(centers, Droot);
    gmm_fused_kernel<<<BATCH / MT, 256, SMEM_TOTAL>>>(x, out);
}